// round 7
// baseline (speedup 1.0000x reference)
#include <cuda_runtime.h>
#include <cuda_bf16.h>

// Shapes (fixed by the problem)
#define B_   32
#define D_   512
#define HID_ 256
#define NF_  8
#define CIN_ 64
#define COUT_ 64
#define HW_  64
#define KK_  3

// Conv tiling
#define OG_   16   // output channels per block
#define TS_   32   // spatial tile (32x32)
#define CC_   16   // cin chunk staged in smem
#define ISTR_ 36   // padded smem row stride (34 cols used), 16B-aligned rows

// -------- device scratch (no allocations allowed) --------
__device__ float g_attn[B_ * NF_];
__device__ float g_aggw[B_ * COUT_ * CIN_ * KK_ * KK_];  // 4.7 MB

// -------- packed fp32x2 FMA (sm_100+ PTX, 2x fp32 throughput) --------
__device__ __forceinline__ void fma2(float2& c, const float2 a, const float2 b) {
    asm("fma.rn.f32x2 %0, %1, %2, %0;"
        : "+l"(reinterpret_cast<unsigned long long&>(c))
        : "l"(reinterpret_cast<const unsigned long long&>(a)),
          "l"(reinterpret_cast<const unsigned long long&>(b)));
}

// ============================================================
// Kernel 1: routing MLP + softmax -> attn [B, NF]
// grid(32), block(256)
// ============================================================
__global__ void routing_kernel(const float* __restrict__ x,
                               const float* __restrict__ w1, const float* __restrict__ b1,
                               const float* __restrict__ w2, const float* __restrict__ b2,
                               float* __restrict__ attn_out, int write_out)
{
    int b = blockIdx.x, t = threadIdx.x;
    __shared__ __align__(16) float xs[D_];
    __shared__ float hs[HID_];
    __shared__ float ls[NF_];
    __shared__ float as_[NF_];

    for (int i = t; i < D_; i += 256) xs[i] = x[b * D_ + i];
    __syncthreads();

    // h[t] = relu(dot(x, w1[t,:]) + b1[t])
    float acc = 0.f;
    const float4* wr = reinterpret_cast<const float4*>(w1 + (size_t)t * D_);
    const float4* xv = reinterpret_cast<const float4*>(xs);
#pragma unroll 8
    for (int k = 0; k < D_ / 4; k++) {
        float4 w4 = wr[k], x4 = xv[k];
        acc += w4.x * x4.x + w4.y * x4.y + w4.z * x4.z + w4.w * x4.w;
    }
    hs[t] = fmaxf(acc + b1[t], 0.f);
    __syncthreads();

    // logits: warp f reduces dot(h, w2[f,:])
    int f = t >> 5, lane = t & 31;
    float s = 0.f;
    for (int j = lane; j < HID_; j += 32) s += hs[j] * w2[f * HID_ + j];
#pragma unroll
    for (int o = 16; o > 0; o >>= 1) s += __shfl_xor_sync(0xffffffffu, s, o);
    if (lane == 0) ls[f] = s + b2[f];
    __syncthreads();

    if (t == 0) {
        float m = -1e30f;
#pragma unroll
        for (int i = 0; i < NF_; i++) m = fmaxf(m, ls[i]);
        float Z = 0.f, e[NF_];
#pragma unroll
        for (int i = 0; i < NF_; i++) { e[i] = expf((ls[i] - m) * (1.0f / 30.0f)); Z += e[i]; }
#pragma unroll
        for (int i = 0; i < NF_; i++) as_[i] = e[i] / Z;
    }
    __syncthreads();
    if (t < NF_) {
        g_attn[b * NF_ + t] = as_[t];
        if (write_out) attn_out[b * NF_ + t] = as_[t];
    }
}

// ============================================================
// Kernel 2: agg_w[b] = sum_f attn[b,f] * W[f]   (float4 streamed)
// grid(36, 32), block(256); 36*256 = 9216 = 64*64*9/4 float4s per sample
// ============================================================
__global__ void agg_kernel(const float* __restrict__ weight)
{
    int b = blockIdx.y;
    int e = blockIdx.x * blockDim.x + threadIdx.x;  // float4 index < 9216
    __shared__ float a[NF_];
    if (threadIdx.x < NF_) a[threadIdx.x] = g_attn[b * NF_ + threadIdx.x];
    __syncthreads();

    const float4* W = reinterpret_cast<const float4*>(weight);
    float4 acc = make_float4(0.f, 0.f, 0.f, 0.f);
#pragma unroll
    for (int f = 0; f < NF_; f++) {
        float4 w = W[(size_t)f * 9216 + e];
        float af = a[f];
        acc.x += af * w.x; acc.y += af * w.y; acc.z += af * w.z; acc.w += af * w.w;
    }
    reinterpret_cast<float4*>(g_aggw)[(size_t)b * 9216 + e] = acc;
}

// ============================================================
// Kernel 3: per-sample 3x3 conv, pad 1.
// grid(4 tiles, 4 o-groups, 32 samples), block(256)
// thread t: oz = t>>6 (4 o-subgroups of 4), (tx,ty) in 8x8, 4x4 pixels each
// ============================================================
__global__ void __launch_bounds__(256, 1)
conv_kernel(const float* __restrict__ x, const float* __restrict__ bias_p,
            float* __restrict__ out)
{
    extern __shared__ float smem[];
    float* w_s  = smem;            // OG_*CIN_*9 = 9216 floats
    float* in_s = smem + 9216;     // CC_*34*ISTR_ = 19584 floats

    const int b    = blockIdx.z;
    const int og   = blockIdx.y;               // 0..3
    const int tile = blockIdx.x;               // 0..3
    const int tile_y = (tile >> 1) * TS_;
    const int tile_x = (tile & 1) * TS_;
    const int t  = threadIdx.x;
    const int oz = t >> 6;
    const int tid6 = t & 63;
    const int tx = tid6 & 7, ty = tid6 >> 3;

    // preload this block's 16 output-channel weight slice (contiguous in g_aggw)
    {
        const float4* wg = reinterpret_cast<const float4*>(
            g_aggw + ((size_t)b * COUT_ + og * OG_) * (CIN_ * 9));
        float4* ws4 = reinterpret_cast<float4*>(w_s);
        for (int i = t; i < 2304; i += 256) ws4[i] = wg[i];
    }

    float2 acc[4][4][2];
#pragma unroll
    for (int o = 0; o < 4; o++)
#pragma unroll
        for (int j = 0; j < 4; j++) {
            acc[o][j][0] = make_float2(0.f, 0.f);
            acc[o][j][1] = make_float2(0.f, 0.f);
        }

    const float* xin = x + (size_t)b * CIN_ * HW_ * HW_;

    for (int cb = 0; cb < CIN_; cb += CC_) {
        __syncthreads();  // protect in_s reuse (and w_s visibility on first iter)
        // stage CC_ input planes (34x34 halo tile, zero-padded at borders)
        for (int idx = t; idx < CC_ * 34 * 34; idx += 256) {
            int ci  = idx / 1156;
            int rem = idx - ci * 1156;
            int r = rem / 34;
            int c = rem - r * 34;
            int gy = tile_y - 1 + r, gx = tile_x - 1 + c;
            float v = 0.f;
            if ((unsigned)gy < (unsigned)HW_ && (unsigned)gx < (unsigned)HW_)
                v = xin[(size_t)(cb + ci) * (HW_ * HW_) + gy * HW_ + gx];
            in_s[(ci * 34 + r) * ISTR_ + c] = v;
        }
        __syncthreads();

        const float* wpz = w_s + (oz * 4) * (CIN_ * 9) + cb * 9;
#pragma unroll 1
        for (int ci = 0; ci < CC_; ci++) {
            // 6x6 input patch -> 5 shifted float2 pairs per row
            float2 p[6][5];
#pragma unroll
            for (int r = 0; r < 6; r++) {
                const float* rp = &in_s[(ci * 34 + ty * 4 + r) * ISTR_ + tx * 4];
                float4 v4 = *reinterpret_cast<const float4*>(rp);
                float2 v2 = *reinterpret_cast<const float2*>(rp + 4);
                p[r][0] = make_float2(v4.x, v4.y);
                p[r][1] = make_float2(v4.y, v4.z);
                p[r][2] = make_float2(v4.z, v4.w);
                p[r][3] = make_float2(v4.w, v2.x);
                p[r][4] = make_float2(v2.x, v2.y);
            }
#pragma unroll
            for (int o = 0; o < 4; o++) {
                const float* w9 = wpz + o * (CIN_ * 9) + ci * 9;
#pragma unroll
                for (int ky = 0; ky < 3; ky++) {
                    float2 s0 = make_float2(w9[ky * 3 + 0], w9[ky * 3 + 0]);
                    float2 s1 = make_float2(w9[ky * 3 + 1], w9[ky * 3 + 1]);
                    float2 s2 = make_float2(w9[ky * 3 + 2], w9[ky * 3 + 2]);
#pragma unroll
                    for (int j = 0; j < 4; j++) {
                        const int r = j + ky;
                        fma2(acc[o][j][0], s0, p[r][0]);
                        fma2(acc[o][j][0], s1, p[r][1]);
                        fma2(acc[o][j][0], s2, p[r][2]);
                        fma2(acc[o][j][1], s0, p[r][2]);
                        fma2(acc[o][j][1], s1, p[r][3]);
                        fma2(acc[o][j][1], s2, p[r][4]);
                    }
                }
            }
        }
    }

    // epilogue: bias[b,o] = sum_f attn[b,f] * bias_p[f,o], vectorized stores
    float at[NF_];
#pragma unroll
    for (int f = 0; f < NF_; f++) at[f] = g_attn[b * NF_ + f];
    const int x0 = tile_x + tx * 4, y0 = tile_y + ty * 4;
#pragma unroll
    for (int o = 0; o < 4; o++) {
        const int oo = og * OG_ + oz * 4 + o;
        float bias = 0.f;
#pragma unroll
        for (int f = 0; f < NF_; f++) bias += at[f] * bias_p[f * COUT_ + oo];
        float* op = out + (((size_t)b * COUT_ + oo) * HW_ + y0) * HW_ + x0;
#pragma unroll
        for (int j = 0; j < 4; j++) {
            float4 v = make_float4(acc[o][j][0].x + bias, acc[o][j][0].y + bias,
                                   acc[o][j][1].x + bias, acc[o][j][1].y + bias);
            *reinterpret_cast<float4*>(op + j * HW_) = v;
        }
    }
}

// ============================================================
extern "C" void kernel_launch(void* const* d_in, const int* in_sizes, int n_in,
                              void* d_out, int out_size)
{
    const float* fc_in   = (const float*)d_in[0];  // [B, D]
    const float* model_in= (const float*)d_in[1];  // [B, CIN, HW, HW]
    const float* fc1_w   = (const float*)d_in[2];  // [HID, D]
    const float* fc1_b   = (const float*)d_in[3];  // [HID]
    const float* fc2_w   = (const float*)d_in[4];  // [NF, HID]
    const float* fc2_b   = (const float*)d_in[5];  // [NF]
    const float* weight  = (const float*)d_in[6];  // [NF, COUT, CIN, 3, 3]
    const float* bias_p  = (const float*)d_in[7];  // [NF, COUT]
    float* out = (float*)d_out;

    const int conv_elems = B_ * COUT_ * HW_ * HW_;        // 8388608
    const int attn_elems = B_ * NF_;                       // 256
    int write_attn = (out_size >= conv_elems + attn_elems) ? 1 : 0;
    float* attn_out = write_attn ? (out + conv_elems) : out;  // dummy when not writing

    routing_kernel<<<B_, 256>>>(fc_in, fc1_w, fc1_b, fc2_w, fc2_b, attn_out, write_attn);
    agg_kernel<<<dim3(36, B_), 256>>>(weight);

    const size_t smem_bytes = (size_t)(9216 + CC_ * 34 * ISTR_) * sizeof(float);  // 115200
    cudaFuncSetAttribute(conv_kernel, cudaFuncAttributeMaxDynamicSharedMemorySize,
                         (int)smem_bytes);
    conv_kernel<<<dim3(4, 4, B_), 256, smem_bytes>>>(model_in, bias_p, out);
}

// round 8
// speedup vs baseline: 2.3717x; 2.3717x over previous
#include <cuda_runtime.h>
#include <cuda_bf16.h>

// Shapes (fixed by the problem)
#define B_   32
#define D_   512
#define HID_ 256
#define NF_  8
#define CIN_ 64
#define COUT_ 64
#define HW_  64

// Conv tiling: block = 16 oc x (32 wide x 16 tall) tile, 256 threads, occ 2
#define OG_   16   // output channels per block
#define TW_   32   // tile width
#define TH_   16   // tile height
#define CC_   16   // cin chunk staged in smem
#define ISTR_ 36   // padded smem input row stride (34 cols used)
#define WSTR_ 18   // weight smem row stride (16 oc + 2 pad, keeps 8B pair alignment)

#define W_S_FLOATS   (CIN_ * 9 * WSTR_)          // 10368
#define IN_S_FLOATS  (CC_ * (TH_ + 2) * ISTR_)   // 16*18*36 = 10368
#define SMEM_FLOATS  (W_S_FLOATS + IN_S_FLOATS)  // 20736 -> 82944 B

// -------- device scratch (no allocations allowed) --------
__device__ float g_attn[B_ * NF_];
__device__ float g_h[B_ * HID_];
__device__ float g_aggw[B_ * COUT_ * CIN_ * 9];  // [b][oc][ci][tap], 4.7 MB

// -------- packed fp32x2 FMA (sm_100+ PTX, 2x fp32 throughput) --------
__device__ __forceinline__ void fma2(float2& c, const float2 a, const float2 b) {
    asm("fma.rn.f32x2 %0, %1, %2, %0;"
        : "+l"(reinterpret_cast<unsigned long long&>(c))
        : "l"(reinterpret_cast<const unsigned long long&>(a)),
          "l"(reinterpret_cast<const unsigned long long&>(b)));
}
__device__ __forceinline__ float2 dup2(float v) { return make_float2(v, v); }

// ============================================================
// Kernel 1a: fc1 -> relu -> g_h.   grid(32, 8), block 256.
// block (b, s) computes h[b, s*32 .. s*32+31]; 8 lanes per hid unit.
// ============================================================
__global__ void fc1_kernel(const float* __restrict__ x,
                           const float* __restrict__ w1, const float* __restrict__ b1)
{
    const int b = blockIdx.x, s = blockIdx.y, t = threadIdx.x;
    __shared__ __align__(16) float xs[D_];
    for (int i = t; i < D_; i += 256) xs[i] = x[b * D_ + i];
    __syncthreads();

    const int u = s * 32 + (t >> 3);   // hid unit
    const int l8 = t & 7;              // lane within unit
    const float4* wr = reinterpret_cast<const float4*>(w1 + (size_t)u * D_);
    const float4* xv = reinterpret_cast<const float4*>(xs);
    float acc = 0.f;
#pragma unroll
    for (int i = 0; i < 16; i++) {
        float4 w4 = wr[l8 + 8 * i], x4 = xv[l8 + 8 * i];
        acc += w4.x * x4.x + w4.y * x4.y + w4.z * x4.z + w4.w * x4.w;
    }
#pragma unroll
    for (int o = 4; o > 0; o >>= 1) acc += __shfl_xor_sync(0xffffffffu, acc, o);
    if (l8 == 0) g_h[b * HID_ + u] = fmaxf(acc + b1[u], 0.f);
}

// ============================================================
// Kernel 1b: fc2 + softmax -> g_attn (+ tuple tail of d_out). grid(32), block 256.
// ============================================================
__global__ void fc2_kernel(const float* __restrict__ w2, const float* __restrict__ b2,
                           float* __restrict__ attn_out, int write_out)
{
    const int b = blockIdx.x, t = threadIdx.x;
    __shared__ float hs[HID_];
    __shared__ float ls[NF_];
    __shared__ float as_[NF_];
    hs[t] = g_h[b * HID_ + t];
    __syncthreads();

    const int f = t >> 5, lane = t & 31;
    float s = 0.f;
#pragma unroll
    for (int i = 0; i < HID_ / 32; i++) s += hs[lane + 32 * i] * w2[f * HID_ + lane + 32 * i];
#pragma unroll
    for (int o = 16; o > 0; o >>= 1) s += __shfl_xor_sync(0xffffffffu, s, o);
    if (lane == 0) ls[f] = s + b2[f];
    __syncthreads();

    if (t == 0) {
        float m = -1e30f;
#pragma unroll
        for (int i = 0; i < NF_; i++) m = fmaxf(m, ls[i]);
        float Z = 0.f, e[NF_];
#pragma unroll
        for (int i = 0; i < NF_; i++) { e[i] = expf((ls[i] - m) * (1.0f / 30.0f)); Z += e[i]; }
#pragma unroll
        for (int i = 0; i < NF_; i++) as_[i] = e[i] / Z;
    }
    __syncthreads();
    if (t < NF_) {
        g_attn[b * NF_ + t] = as_[t];
        if (write_out) attn_out[b * NF_ + t] = as_[t];
    }
}

// ============================================================
// Kernel 2: agg_w[b] = sum_f attn[b,f] * W[f]   (float4 streamed)
// grid(36, 32), block 256; 36*256 = 9216 float4s per sample.
// ============================================================
__global__ void agg_kernel(const float* __restrict__ weight)
{
    const int b = blockIdx.y;
    const int e = blockIdx.x * blockDim.x + threadIdx.x;
    __shared__ float a[NF_];
    if (threadIdx.x < NF_) a[threadIdx.x] = g_attn[b * NF_ + threadIdx.x];
    __syncthreads();

    const float4* W = reinterpret_cast<const float4*>(weight);
    float4 acc = make_float4(0.f, 0.f, 0.f, 0.f);
#pragma unroll
    for (int f = 0; f < NF_; f++) {
        float4 w = W[(size_t)f * 9216 + e];
        float af = a[f];
        acc.x += af * w.x; acc.y += af * w.y; acc.z += af * w.z; acc.w += af * w.w;
    }
    reinterpret_cast<float4*>(g_aggw)[(size_t)b * 9216 + e] = acc;
}

// ============================================================
// Kernel 3: per-sample 3x3 conv, pad 1. f32x2 over OUTPUT-CHANNEL pairs.
// grid(8 tiles[32x16], 4 og, 32 b), block 256, 2 CTAs/SM.
// thread: oh = t>>7 (oc-half, 8 ch as 4 pairs), row = (t&127)>>3, cg = t&7 (4 px).
// ============================================================
__global__ void __launch_bounds__(256, 2)
conv_kernel(const float* __restrict__ x, const float* __restrict__ bias_p,
            float* __restrict__ out)
{
    extern __shared__ float smem[];
    float* w_s  = smem;                 // [ci*9+tap][oc16], stride WSTR_
    float* in_s = smem + W_S_FLOATS;    // [ci][18 rows][ISTR_]

    const int b    = blockIdx.z;
    const int og   = blockIdx.y;                 // 0..3
    const int tile = blockIdx.x;                 // 0..7
    const int tile_y = (tile >> 1) * TH_;
    const int tile_x = (tile & 1) * TW_;
    const int t   = threadIdx.x;
    const int oh  = t >> 7;                      // 0..1 (oc half)
    const int pt  = t & 127;
    const int row = pt >> 3;                     // 0..15
    const int x0  = (pt & 7) * 4;                // 0..28

    // prologue: transpose this block's 16-oc weight slice into interleaved smem
    {
        const float* wg = g_aggw + ((size_t)b * COUT_ + og * OG_) * (CIN_ * 9);
        for (int idx = t; idx < OG_ * CIN_ * 9; idx += 256) {
            int oc16 = idx / (CIN_ * 9);
            int r    = idx - oc16 * (CIN_ * 9);   // ci*9 + tap
            w_s[r * WSTR_ + oc16] = wg[(size_t)oc16 * (CIN_ * 9) + r];
        }
    }

    float2 acc[4][4];                    // [oc-pair][px]
#pragma unroll
    for (int p = 0; p < 4; p++)
#pragma unroll
        for (int j = 0; j < 4; j++) acc[p][j] = make_float2(0.f, 0.f);

    const float* xin = x + (size_t)b * CIN_ * HW_ * HW_;

    for (int cb = 0; cb < CIN_; cb += CC_) {
        __syncthreads();  // in_s reuse (and w_s visibility on first iter)
        // stage CC_ input planes, (TH_+2) x 34 halo tile, zero-padded at borders
        for (int idx = t; idx < CC_ * (TH_ + 2) * 34; idx += 256) {
            int ci  = idx / ((TH_ + 2) * 34);
            int rem = idx - ci * ((TH_ + 2) * 34);
            int r = rem / 34;
            int c = rem - r * 34;
            int gy = tile_y - 1 + r, gx = tile_x - 1 + c;
            float v = 0.f;
            if ((unsigned)gy < (unsigned)HW_ && (unsigned)gx < (unsigned)HW_)
                v = xin[(size_t)(cb + ci) * (HW_ * HW_) + gy * HW_ + gx];
            in_s[(ci * (TH_ + 2) + r) * ISTR_ + c] = v;
        }
        __syncthreads();

#pragma unroll 1
        for (int ci = 0; ci < CC_; ci++) {
            // 3x6 input patch, duplicated into f32x2 pairs
            float2 d[3][6];
#pragma unroll
            for (int rr = 0; rr < 3; rr++) {
                const float* rp = &in_s[(ci * (TH_ + 2) + row + rr) * ISTR_ + x0];
                float4 v4 = *reinterpret_cast<const float4*>(rp);
                float2 v2 = *reinterpret_cast<const float2*>(rp + 4);
                d[rr][0] = dup2(v4.x); d[rr][1] = dup2(v4.y); d[rr][2] = dup2(v4.z);
                d[rr][3] = dup2(v4.w); d[rr][4] = dup2(v2.x); d[rr][5] = dup2(v2.y);
            }
            const float* wci = w_s + (cb + ci) * 9 * WSTR_ + oh * 8;
#pragma unroll
            for (int ky = 0; ky < 3; ky++) {
#pragma unroll
                for (int kx = 0; kx < 3; kx++) {
                    // 4 oc-pair weights for this tap: broadcast LDS.64, no packing
                    const float2* wp = reinterpret_cast<const float2*>(
                        wci + (ky * 3 + kx) * WSTR_);
                    float2 w0 = wp[0], w1 = wp[1], w2 = wp[2], w3 = wp[3];
#pragma unroll
                    for (int j = 0; j < 4; j++) {
                        const float2 iv = d[ky][j + kx];
                        fma2(acc[0][j], w0, iv);
                        fma2(acc[1][j], w1, iv);
                        fma2(acc[2][j], w2, iv);
                        fma2(acc[3][j], w3, iv);
                    }
                }
            }
        }
    }

    // epilogue: bias[b,oc] = sum_f attn[b,f] * bias_p[f,oc]; float4 stores
    float at[NF_];
#pragma unroll
    for (int f = 0; f < NF_; f++) at[f] = g_attn[b * NF_ + f];
    const int gx0 = tile_x + x0, gy0 = tile_y + row;
#pragma unroll
    for (int p = 0; p < 4; p++) {
        const int oc = og * OG_ + oh * 8 + 2 * p;
        float ba = 0.f, bb = 0.f;
#pragma unroll
        for (int f = 0; f < NF_; f++) {
            ba += at[f] * bias_p[f * COUT_ + oc];
            bb += at[f] * bias_p[f * COUT_ + oc + 1];
        }
        float* opa = out + (((size_t)b * COUT_ + oc) * HW_ + gy0) * HW_ + gx0;
        float* opb = opa + (size_t)HW_ * HW_;
        *reinterpret_cast<float4*>(opa) =
            make_float4(acc[p][0].x + ba, acc[p][1].x + ba, acc[p][2].x + ba, acc[p][3].x + ba);
        *reinterpret_cast<float4*>(opb) =
            make_float4(acc[p][0].y + bb, acc[p][1].y + bb, acc[p][2].y + bb, acc[p][3].y + bb);
    }
}

// ============================================================
extern "C" void kernel_launch(void* const* d_in, const int* in_sizes, int n_in,
                              void* d_out, int out_size)
{
    const float* fc_in    = (const float*)d_in[0];  // [B, D]
    const float* model_in = (const float*)d_in[1];  // [B, CIN, HW, HW]
    const float* fc1_w    = (const float*)d_in[2];  // [HID, D]
    const float* fc1_b    = (const float*)d_in[3];  // [HID]
    const float* fc2_w    = (const float*)d_in[4];  // [NF, HID]
    const float* fc2_b    = (const float*)d_in[5];  // [NF]
    const float* weight   = (const float*)d_in[6];  // [NF, COUT, CIN, 3, 3]
    const float* bias_p   = (const float*)d_in[7];  // [NF, COUT]
    float* out = (float*)d_out;

    const int conv_elems = B_ * COUT_ * HW_ * HW_;        // 8388608
    const int attn_elems = B_ * NF_;                       // 256
    int write_attn = (out_size >= conv_elems + attn_elems) ? 1 : 0;
    float* attn_out = write_attn ? (out + conv_elems) : out;

    fc1_kernel<<<dim3(B_, 8), 256>>>(fc_in, fc1_w, fc1_b);
    fc2_kernel<<<B_, 256>>>(fc2_w, fc2_b, attn_out, write_attn);
    agg_kernel<<<dim3(36, B_), 256>>>(weight);

    const size_t smem_bytes = (size_t)SMEM_FLOATS * sizeof(float);  // 82944
    cudaFuncSetAttribute(conv_kernel, cudaFuncAttributeMaxDynamicSharedMemorySize,
                         (int)smem_bytes);
    conv_kernel<<<dim3(8, 4, B_), 256, smem_bytes>>>(model_in, bias_p, out);
}